// round 12
// baseline (speedup 1.0000x reference)
#include <cuda_runtime.h>
#include <cuda_bf16.h>
#include <stdint.h>
#include <math.h>

// Problem dims (fixed)
#define MTOT 4096   // B*N
#define ETOT 1024
#define SEQ  2048
#define NH   16
#define HDIM 64

// ---------------- scratch (device globals) ----------------
__device__ __nv_bfloat16 g_x2[4096 * 2048];        // x split  [4096][hi 1024 | lo 1024]
__device__ __nv_bfloat16 g_w5[5120 * 2048];        // W splits packed rows: q,k,v,u,o
__device__ __nv_bfloat16 g_g2[4096 * 2048];        // gate split [hi|lo]
__device__ __nv_bfloat16 g_q2[32 * 2048 * 128];    // [bh][n][hi 64 | lo 64]
__device__ __nv_bfloat16 g_k2[32 * 2048 * 128];
__device__ __nv_bfloat16 g_v2[32 * 2048 * 128];
__device__ float g_u[4096 * 1024];
__device__ float g_attn[4096 * 1024];

// ---------------- helpers ----------------
__device__ __forceinline__ unsigned smem_u32(const void* p) {
    return (unsigned)__cvta_generic_to_shared(p);
}
__device__ __forceinline__ void ldmat_x4(unsigned addr, unsigned* r) {
    asm volatile("ldmatrix.sync.aligned.m8n8.x4.shared.b16 {%0,%1,%2,%3}, [%4];\n"
                 : "=r"(r[0]), "=r"(r[1]), "=r"(r[2]), "=r"(r[3]) : "r"(addr));
}
__device__ __forceinline__ void ldmat_x4_t(unsigned addr, unsigned* r) {
    asm volatile("ldmatrix.sync.aligned.m8n8.x4.trans.shared.b16 {%0,%1,%2,%3}, [%4];\n"
                 : "=r"(r[0]), "=r"(r[1]), "=r"(r[2]), "=r"(r[3]) : "r"(addr));
}
__device__ __forceinline__ void mma_bf16(float* c, const unsigned* a, const unsigned* b) {
    asm volatile(
        "mma.sync.aligned.m16n8k16.row.col.f32.bf16.bf16.f32 "
        "{%0,%1,%2,%3}, {%4,%5,%6,%7}, {%8,%9}, {%0,%1,%2,%3};\n"
        : "+f"(c[0]), "+f"(c[1]), "+f"(c[2]), "+f"(c[3])
        : "r"(a[0]), "r"(a[1]), "r"(a[2]), "r"(a[3]), "r"(b[0]), "r"(b[1]));
}
__device__ __forceinline__ void split_bf16(float x, __nv_bfloat16& hi, __nv_bfloat16& lo) {
    hi = __float2bfloat16(x);
    lo = __float2bfloat16(x - __bfloat162float(hi));
}
__device__ __forceinline__ unsigned pack2(__nv_bfloat16 a, __nv_bfloat16 b) {
    __nv_bfloat162 t; t.x = a; t.y = b;
    return *(unsigned*)&t;
}
__device__ __forceinline__ void cp16(unsigned dst, const void* src) {
    asm volatile("cp.async.cg.shared.global [%0], [%1], 16;\n" :: "r"(dst), "l"(src));
}
__device__ __forceinline__ void cp_commit() { asm volatile("cp.async.commit_group;\n"); }
__device__ __forceinline__ void cp_wait0()  { asm volatile("cp.async.wait_group 0;\n" ::: "memory"); }
__device__ __forceinline__ void cp_wait1()  { asm volatile("cp.async.wait_group 1;\n" ::: "memory"); }

// ---------------- unified split: x + 5 weights, one launch ----------------
__global__ __launch_bounds__(256) void split_all_kernel(
    const float* __restrict__ x,
    const float* __restrict__ w0, const float* __restrict__ w1,
    const float* __restrict__ w2, const float* __restrict__ w3,
    const float* __restrict__ w4,
    __nv_bfloat16* __restrict__ outX, __nv_bfloat16* __restrict__ outW)
{
    int row = blockIdx.x;
    int c = threadIdx.x << 2;
    const float* src;
    __nv_bfloat16* dst;
    if (row < 4096) {
        src = x + (size_t)row * 1024;
        dst = outX + (size_t)row * 2048;
    } else {
        int wrow = row - 4096;
        int which = wrow >> 10;
        int r = wrow & 1023;
        const float* w = (which == 0) ? w0 : (which == 1) ? w1 :
                         (which == 2) ? w2 : (which == 3) ? w3 : w4;
        src = w + (size_t)r * 1024;
        dst = outW + (size_t)wrow * 2048;
    }
    float4 a = *(const float4*)&src[c];
    __nv_bfloat16 h0, h1, h2, h3, l0, l1, l2, l3;
    split_bf16(a.x, h0, l0); split_bf16(a.y, h1, l1);
    split_bf16(a.z, h2, l2); split_bf16(a.w, h3, l3);
    uint2 hv; hv.x = pack2(h0, h1); hv.y = pack2(h2, h3);
    uint2 lv; lv.x = pack2(l0, l1); lv.y = pack2(l2, l3);
    *(uint2*)&dst[c] = hv;
    *(uint2*)&dst[1024 + c] = lv;
}

// ================= projection GEMM core (3-stage cp.async, 2 CTAs/SM) =================
#define PPITCH 72
#define PSTG_ELEM (2 * 128 * PPITCH)          // bf16 elems per stage (A+B)
#define PROJ_SMEM (3 * PSTG_ELEM * 2)         // 110,592 B/CTA; x2 CTAs = 221,184 <= 228KB

__device__ __forceinline__ void proj_load_chunk(
    const __nv_bfloat16* __restrict__ A2, const __nv_bfloat16* __restrict__ B2,
    __nv_bfloat16* As, __nv_bfloat16* Bs, int mB, int nB, int kb, int tid)
{
#pragma unroll
    for (int t = 0; t < 4; t++) {
        int idx = tid + t * 256;            // 0..1023
        int row = idx >> 3, s = idx & 7;    // 8 x 16B slices per row
        int gcol = (s < 4) ? (kb + s * 8) : (1024 + kb + (s - 4) * 8);
        int scol = (s < 4) ? (s * 8) : (32 + (s - 4) * 8);
        cp16(smem_u32(&As[row * PPITCH + scol]), &A2[(size_t)(mB + row) * 2048 + gcol]);
        cp16(smem_u32(&Bs[row * PPITCH + scol]), &B2[(size_t)(nB + row) * 2048 + gcol]);
    }
}

__device__ __forceinline__ void proj_mainloop(
    const __nv_bfloat16* __restrict__ A2, const __nv_bfloat16* __restrict__ B2,
    __nv_bfloat16* smb, int mB, int nB, int tid, int lane,
    int warpM, int warpN, float acc[2][8][4])
{
#pragma unroll
    for (int mt = 0; mt < 2; mt++)
#pragma unroll
        for (int nt = 0; nt < 8; nt++)
#pragma unroll
            for (int r = 0; r < 4; r++) acc[mt][nt][r] = 0.f;

    __nv_bfloat16* stA[3] = { smb, smb + PSTG_ELEM, smb + 2 * PSTG_ELEM };
    proj_load_chunk(A2, B2, stA[0], stA[0] + 128 * PPITCH, mB, nB, 0, tid);
    cp_commit();
    proj_load_chunk(A2, B2, stA[1], stA[1] + 128 * PPITCH, mB, nB, 32, tid);
    cp_commit();

    for (int c = 0; c < 32; c++) {
        if (c < 31) cp_wait1(); else cp_wait0();
        __syncthreads();   // chunk c ready; all warps done with stage (c+2)%3
        if (c + 2 < 32) {
            __nv_bfloat16* st = stA[(c + 2) % 3];
            proj_load_chunk(A2, B2, st, st + 128 * PPITCH, mB, nB, (c + 2) * 32, tid);
            cp_commit();
        }

        const __nv_bfloat16* As = stA[c % 3];
        const __nv_bfloat16* Bs = As + 128 * PPITCH;
#pragma unroll
        for (int ks = 0; ks < 2; ks++) {
            const int kk = ks * 16;
            unsigned ahi[2][4], alo[2][4];
#pragma unroll
            for (int mt = 0; mt < 2; mt++) {
                int arow = warpM * 32 + mt * 16 + (lane & 15);
                int ako = kk + ((lane >> 4) << 3);
                ldmat_x4(smem_u32(&As[arow * PPITCH + ako]), ahi[mt]);
                ldmat_x4(smem_u32(&As[arow * PPITCH + 32 + ako]), alo[mt]);
            }
            // process p in pairs; preload both B fragments, emit term-outer
#pragma unroll
            for (int pp = 0; pp < 2; pp++) {
                unsigned bh_[2][4], bl_[2][4];
#pragma unroll
                for (int p2 = 0; p2 < 2; p2++) {
                    int p = pp * 2 + p2;
                    int nrow = warpN * 64 + p * 16 + ((lane >> 4) << 3) + (lane & 7);
                    int kc = kk + (((lane >> 3) & 1) << 3);
                    ldmat_x4(smem_u32(&Bs[nrow * PPITCH + kc]), bh_[p2]);
                    ldmat_x4(smem_u32(&Bs[nrow * PPITCH + 32 + kc]), bl_[p2]);
                }
                // term 1: ahi x bh — 8 MMAs before any acc repeats
#pragma unroll
                for (int p2 = 0; p2 < 2; p2++)
#pragma unroll
                    for (int mt = 0; mt < 2; mt++) {
                        int p = pp * 2 + p2;
                        mma_bf16(acc[mt][2 * p],     ahi[mt], &bh_[p2][0]);
                        mma_bf16(acc[mt][2 * p + 1], ahi[mt], &bh_[p2][2]);
                    }
                // term 2: alo x bh
#pragma unroll
                for (int p2 = 0; p2 < 2; p2++)
#pragma unroll
                    for (int mt = 0; mt < 2; mt++) {
                        int p = pp * 2 + p2;
                        mma_bf16(acc[mt][2 * p],     alo[mt], &bh_[p2][0]);
                        mma_bf16(acc[mt][2 * p + 1], alo[mt], &bh_[p2][2]);
                    }
                // term 3: ahi x bl
#pragma unroll
                for (int p2 = 0; p2 < 2; p2++)
#pragma unroll
                    for (int mt = 0; mt < 2; mt++) {
                        int p = pp * 2 + p2;
                        mma_bf16(acc[mt][2 * p],     ahi[mt], &bl_[p2][0]);
                        mma_bf16(acc[mt][2 * p + 1], ahi[mt], &bl_[p2][2]);
                    }
            }
        }
    }
}

// ---- fused Q/K/V/U projection: grid (32,32) ----
__global__ __launch_bounds__(256, 2) void proj_fused(
    const __nv_bfloat16* __restrict__ A2, const __nv_bfloat16* __restrict__ W2,
    const float* __restrict__ b0, const float* __restrict__ b1,
    const float* __restrict__ b2, const float* __restrict__ b3,
    __nv_bfloat16* __restrict__ outQ, __nv_bfloat16* __restrict__ outK,
    __nv_bfloat16* __restrict__ outV, float* __restrict__ outU)
{
    extern __shared__ __nv_bfloat16 smb[];
    const int tid = threadIdx.x;
    const int lane = tid & 31, warp = tid >> 5;
    const int warpM = warp >> 1, warpN = warp & 1;
    const int mB = blockIdx.y * 128, nB = blockIdx.x * 128;
    const int g = lane >> 2, tig = lane & 3;
    const int which = nB >> 10;

    float acc[2][8][4];
    proj_mainloop(A2, W2, smb, mB, nB, tid, lane, warpM, warpN, acc);

    const float* bp = (which == 0) ? b0 : (which == 1) ? b1 : (which == 2) ? b2 : b3;
    __nv_bfloat16* outH = (which == 0) ? outQ : (which == 1) ? outK : outV;
    const int act = (which >= 2);

#pragma unroll
    for (int mt = 0; mt < 2; mt++)
#pragma unroll
        for (int nt = 0; nt < 8; nt++)
#pragma unroll
            for (int rp = 0; rp < 2; rp++) {
                int m = mB + warpM * 32 + mt * 16 + g + rp * 8;
                int e0 = nB + warpN * 64 + nt * 8 + 2 * tig;
                int eq = e0 & 1023;
                float v0 = acc[mt][nt][rp * 2]     + __ldg(&bp[eq]);
                float v1 = acc[mt][nt][rp * 2 + 1] + __ldg(&bp[eq + 1]);
                if (act) {
                    v0 = v0 / (1.f + __expf(-v0));
                    v1 = v1 / (1.f + __expf(-v1));
                }
                if (which == 3) {
                    float2 fv; fv.x = v0; fv.y = v1;
                    *(float2*)&outU[(size_t)m * ETOT + eq] = fv;
                } else {
                    int b = m >> 11, n = m & (SEQ - 1);
                    int h = eq >> 6, d = eq & (HDIM - 1);
                    __nv_bfloat16 h0, h1, l0, l1;
                    split_bf16(v0, h0, l0);
                    split_bf16(v1, h1, l1);
                    size_t base = (((size_t)b * NH + h) * SEQ + n) * 128 + d;
                    *(unsigned*)&outH[base]      = pack2(h0, h1);
                    *(unsigned*)&outH[base + 64] = pack2(l0, l1);
                }
            }
}

// ---- output projection: grid (8,32) ----
__global__ __launch_bounds__(256, 2) void proj_out(
    const __nv_bfloat16* __restrict__ A2, const __nv_bfloat16* __restrict__ W2,
    const float* __restrict__ bias, float* __restrict__ outF)
{
    extern __shared__ __nv_bfloat16 smb[];
    const int tid = threadIdx.x;
    const int lane = tid & 31, warp = tid >> 5;
    const int warpM = warp >> 1, warpN = warp & 1;
    const int mB = blockIdx.y * 128, nB = blockIdx.x * 128;
    const int g = lane >> 2, tig = lane & 3;

    float acc[2][8][4];
    proj_mainloop(A2, W2, smb, mB, nB, tid, lane, warpM, warpN, acc);

#pragma unroll
    for (int mt = 0; mt < 2; mt++)
#pragma unroll
        for (int nt = 0; nt < 8; nt++)
#pragma unroll
            for (int rp = 0; rp < 2; rp++) {
                int m = mB + warpM * 32 + mt * 16 + g + rp * 8;
                int e0 = nB + warpN * 64 + nt * 8 + 2 * tig;
                float2 fv;
                fv.x = acc[mt][nt][rp * 2]     + __ldg(&bias[e0]);
                fv.y = acc[mt][nt][rp * 2 + 1] + __ldg(&bias[e0 + 1]);
                *(float2*)&outF[(size_t)m * ETOT + e0] = fv;
            }
}

// ================= attention: S-in-registers, double-buffered K/V =================
#define QPITCH 136
#define VPITCH 72
#define KS_ELEM (64 * QPITCH)
#define VS_ELEM (128 * VPITCH)
#define ATTN_SMEM ((128 * QPITCH + 2 * KS_ELEM + 2 * VS_ELEM) * 2)

__device__ __forceinline__ void attn_load_kv(
    const __nv_bfloat16* kp, const __nv_bfloat16* vp,
    __nv_bfloat16* Ks, __nv_bfloat16* Vs, int kt, int tid)
{
#pragma unroll
    for (int t = 0; t < 4; t++) {
        int idx = tid + t * 256;
        int row = idx >> 4, s = idx & 15;
        cp16(smem_u32(&Ks[row * QPITCH + s * 8]), &kp[(size_t)(kt + row) * 128 + s * 8]);
        if (s < 8)
            cp16(smem_u32(&Vs[row * VPITCH + s * 8]), &vp[(size_t)(kt + row) * 128 + s * 8]);
        else
            cp16(smem_u32(&Vs[(64 + row) * VPITCH + (s - 8) * 8]),
                 &vp[(size_t)(kt + row) * 128 + s * 8]);
    }
}

__global__ __launch_bounds__(256, 2) void attn_mma3(
    const __nv_bfloat16* __restrict__ q2, const __nv_bfloat16* __restrict__ k2,
    const __nv_bfloat16* __restrict__ v2, float* __restrict__ attn)
{
    extern __shared__ __nv_bfloat16 smb[];
    __nv_bfloat16* Qs  = smb;                       // [128][136]
    __nv_bfloat16* Ks0 = Qs + 128 * QPITCH;         // [2][64][136]
    __nv_bfloat16* Vs0 = Ks0 + 2 * KS_ELEM;         // [2][128][72]

    const int tid = threadIdx.x;
    const int lane = tid & 31, warp = tid >> 5;     // warp 0..7 = m16 strip
    const int g = lane >> 2, tig = lane & 3;
    const int sel = lane >> 3, l8 = lane & 7;
    const int bh = blockIdx.y;
    const int qBase = blockIdx.x * 128;
    const __nv_bfloat16* qp = q2 + (size_t)bh * SEQ * 128;
    const __nv_bfloat16* kp = k2 + (size_t)bh * SEQ * 128;
    const __nv_bfloat16* vp = v2 + (size_t)bh * SEQ * 128;

    // Q (persistent)
#pragma unroll
    for (int t = 0; t < 8; t++) {
        int idx = tid + t * 256;
        int row = idx >> 4, s = idx & 15;
        cp16(smem_u32(&Qs[row * QPITCH + s * 8]), &qp[(size_t)(qBase + row) * 128 + s * 8]);
    }
    cp_commit();
    attn_load_kv(kp, vp, Ks0, Vs0, 0, tid);
    cp_commit();

    float oacc[8][4];
#pragma unroll
    for (int nt = 0; nt < 8; nt++)
#pragma unroll
        for (int r = 0; r < 4; r++) oacc[nt][r] = 0.f;

    for (int tile = 0; tile < 32; tile++) {
        const int buf = tile & 1;
        cp_wait0();
        __syncthreads();
        if (tile + 1 < 32) {
            attn_load_kv(kp, vp, Ks0 + (buf ^ 1) * KS_ELEM, Vs0 + (buf ^ 1) * VS_ELEM,
                         (tile + 1) * 64, tid);
            cp_commit();
        }
        const __nv_bfloat16* Ks = Ks0 + buf * KS_ELEM;
        const __nv_bfloat16* Vs = Vs0 + buf * VS_ELEM;

        // ---- phase 2: S[m16][64] = Q K^T (3-term, p-pair preload, term-outer) ----
        float sacc[8][4];
#pragma unroll
        for (int nt = 0; nt < 8; nt++)
#pragma unroll
            for (int r = 0; r < 4; r++) sacc[nt][r] = 0.f;

#pragma unroll
        for (int ks = 0; ks < 4; ks++) {
            const int kk = ks * 16;
            unsigned qhi[4], qlo[4];
            int arow = warp * 16 + (lane & 15);
            int ako = kk + ((lane >> 4) << 3);
            ldmat_x4(smem_u32(&Qs[arow * QPITCH + ako]), qhi);
            ldmat_x4(smem_u32(&Qs[arow * QPITCH + 64 + ako]), qlo);
#pragma unroll
            for (int pp = 0; pp < 2; pp++) {
                unsigned kh_[2][4], kl_[2][4];
#pragma unroll
                for (int p2 = 0; p2 < 2; p2++) {
                    int p = pp * 2 + p2;
                    int jrow = p * 16 + ((lane >> 4) << 3) + (lane & 7);
                    int kc = kk + (((lane >> 3) & 1) << 3);
                    ldmat_x4(smem_u32(&Ks[jrow * QPITCH + kc]), kh_[p2]);
                    ldmat_x4(smem_u32(&Ks[jrow * QPITCH + 64 + kc]), kl_[p2]);
                }
#pragma unroll
                for (int p2 = 0; p2 < 2; p2++) {
                    int p = pp * 2 + p2;
                    mma_bf16(sacc[2 * p],     qhi, &kh_[p2][0]);
                    mma_bf16(sacc[2 * p + 1], qhi, &kh_[p2][2]);
                }
#pragma unroll
                for (int p2 = 0; p2 < 2; p2++) {
                    int p = pp * 2 + p2;
                    mma_bf16(sacc[2 * p],     qlo, &kh_[p2][0]);
                    mma_bf16(sacc[2 * p + 1], qlo, &kh_[p2][2]);
                }
#pragma unroll
                for (int p2 = 0; p2 < 2; p2++) {
                    int p = pp * 2 + p2;
                    mma_bf16(sacc[2 * p],     qhi, &kl_[p2][0]);
                    mma_bf16(sacc[2 * p + 1], qhi, &kl_[p2][2]);
                }
            }
        }

        // ---- phase 3: O += S V (S converted in regs, p-pair preload, term-outer) ----
#pragma unroll
        for (int t = 0; t < 4; t++) {
            unsigned ah[4], al[4];
#pragma unroll
            for (int j = 0; j < 2; j++) {
                float* s = sacc[2 * t + j];
                float s0 = s[0] * 0.125f, s1 = s[1] * 0.125f;
                float s2 = s[2] * 0.125f, s3 = s[3] * 0.125f;
                s0 = s0 > 0.f ? s0 : 0.f;  s1 = s1 > 0.f ? s1 : 0.f;
                s2 = s2 > 0.f ? s2 : 0.f;  s3 = s3 > 0.f ? s3 : 0.f;
                __nv_bfloat16 h0, h1, h2, h3, l0, l1, l2, l3;
                split_bf16(s0, h0, l0); split_bf16(s1, h1, l1);
                split_bf16(s2, h2, l2); split_bf16(s3, h3, l3);
                ah[2 * j]     = pack2(h0, h1);
                ah[2 * j + 1] = pack2(h2, h3);
                al[2 * j]     = pack2(l0, l1);
                al[2 * j + 1] = pack2(l2, l3);
            }
#pragma unroll
            for (int pp = 0; pp < 2; pp++) {
                unsigned vh_[2][4], vl_[2][4];
#pragma unroll
                for (int p2 = 0; p2 < 2; p2++) {
                    int p = pp * 2 + p2;
                    int krh = t * 16 + ((sel & 1) << 3) + l8;
                    int nc = p * 16 + ((sel >> 1) << 3);
                    ldmat_x4_t(smem_u32(&Vs[krh * VPITCH + nc]), vh_[p2]);
                    ldmat_x4_t(smem_u32(&Vs[(64 + krh) * VPITCH + nc]), vl_[p2]);
                }
#pragma unroll
                for (int p2 = 0; p2 < 2; p2++) {
                    int p = pp * 2 + p2;
                    mma_bf16(oacc[2 * p],     ah, &vh_[p2][0]);
                    mma_bf16(oacc[2 * p + 1], ah, &vh_[p2][2]);
                }
#pragma unroll
                for (int p2 = 0; p2 < 2; p2++) {
                    int p = pp * 2 + p2;
                    mma_bf16(oacc[2 * p],     al, &vh_[p2][0]);
                    mma_bf16(oacc[2 * p + 1], al, &vh_[p2][2]);
                }
#pragma unroll
                for (int p2 = 0; p2 < 2; p2++) {
                    int p = pp * 2 + p2;
                    mma_bf16(oacc[2 * p],     ah, &vl_[p2][0]);
                    mma_bf16(oacc[2 * p + 1], ah, &vl_[p2][2]);
                }
            }
        }
    }

    const int b = bh >> 4, h = bh & 15;
#pragma unroll
    for (int nt = 0; nt < 8; nt++)
#pragma unroll
        for (int rp = 0; rp < 2; rp++) {
            int row = qBase + warp * 16 + g + rp * 8;
            int d0 = nt * 8 + 2 * tig;
            float2 fv;
            fv.x = oacc[nt][rp * 2];
            fv.y = oacc[nt][rp * 2 + 1];
            *(float2*)&attn[((size_t)b * SEQ + row) * ETOT + h * HDIM + d0] = fv;
        }
}

// ---------------- layernorm + gate; writes split bf16 gate ----------------
__global__ __launch_bounds__(256) void ln_gate(
    const float* __restrict__ a, const float* __restrict__ u,
    const float* __restrict__ gamma, const float* __restrict__ beta,
    __nv_bfloat16* __restrict__ o2)
{
    const int row = blockIdx.x;
    const int tid = threadIdx.x;
    const float* ar = a + (size_t)row * ETOT;
    float4 xv = *(const float4*)&ar[tid * 4];

    float s1 = xv.x + xv.y + xv.z + xv.w;
    float s2 = xv.x * xv.x + xv.y * xv.y + xv.z * xv.z + xv.w * xv.w;
#pragma unroll
    for (int o = 16; o > 0; o >>= 1) {
        s1 += __shfl_xor_sync(0xffffffffu, s1, o);
        s2 += __shfl_xor_sync(0xffffffffu, s2, o);
    }
    __shared__ float r1[8], r2[8];
    __shared__ float mu_s, inv_s;
    if ((tid & 31) == 0) { r1[tid >> 5] = s1; r2[tid >> 5] = s2; }
    __syncthreads();
    if (tid == 0) {
        float t1 = 0.f, t2 = 0.f;
#pragma unroll
        for (int i = 0; i < 8; i++) { t1 += r1[i]; t2 += r2[i]; }
        float mu = t1 * (1.f / ETOT);
        float var = t2 * (1.f / ETOT) - mu * mu;
        mu_s = mu;
        inv_s = rsqrtf(var + 1e-5f);
    }
    __syncthreads();
    const float mu = mu_s, inv = inv_s;

    float4 gv = *(const float4*)&gamma[tid * 4];
    float4 bv = *(const float4*)&beta[tid * 4];
    float4 uv = *(const float4*)&u[(size_t)row * ETOT + tid * 4];
    float o0 = ((xv.x - mu) * inv * gv.x + bv.x) * uv.x;
    float o1 = ((xv.y - mu) * inv * gv.y + bv.y) * uv.y;
    float o2v = ((xv.z - mu) * inv * gv.z + bv.z) * uv.z;
    float o3 = ((xv.w - mu) * inv * gv.w + bv.w) * uv.w;
    __nv_bfloat16 h0, h1, h2, h3, l0, l1, l2, l3;
    split_bf16(o0, h0, l0); split_bf16(o1, h1, l1);
    split_bf16(o2v, h2, l2); split_bf16(o3, h3, l3);
    uint2 hv; hv.x = pack2(h0, h1); hv.y = pack2(h2, h3);
    uint2 lv; lv.x = pack2(l0, l1); lv.y = pack2(l2, l3);
    *(uint2*)&o2[(size_t)row * 2048 + tid * 4]        = hv;
    *(uint2*)&o2[(size_t)row * 2048 + 1024 + tid * 4] = lv;
}

// ---------------- launch ----------------
extern "C" void kernel_launch(void* const* d_in, const int* in_sizes, int n_in,
                              void* d_out, int out_size)
{
    const float* x    = (const float*)d_in[0];
    const float* Wq   = (const float*)d_in[1];
    const float* bq   = (const float*)d_in[2];
    const float* Wk   = (const float*)d_in[3];
    const float* bk   = (const float*)d_in[4];
    const float* Wv   = (const float*)d_in[5];
    const float* bv   = (const float*)d_in[6];
    const float* Wu   = (const float*)d_in[7];
    const float* bu   = (const float*)d_in[8];
    const float* Wo   = (const float*)d_in[9];
    const float* bo   = (const float*)d_in[10];
    const float* ln_g = (const float*)d_in[11];
    const float* ln_b = (const float*)d_in[12];

    __nv_bfloat16 *x2, *w5, *g2, *q2, *k2, *v2;
    float *up, *ap;
    cudaGetSymbolAddress((void**)&x2, g_x2);
    cudaGetSymbolAddress((void**)&w5, g_w5);
    cudaGetSymbolAddress((void**)&g2, g_g2);
    cudaGetSymbolAddress((void**)&q2, g_q2);
    cudaGetSymbolAddress((void**)&k2, g_k2);
    cudaGetSymbolAddress((void**)&v2, g_v2);
    cudaGetSymbolAddress((void**)&up, g_u);
    cudaGetSymbolAddress((void**)&ap, g_attn);

    cudaFuncSetAttribute(proj_fused,
                         cudaFuncAttributeMaxDynamicSharedMemorySize, PROJ_SMEM);
    cudaFuncSetAttribute(proj_out,
                         cudaFuncAttributeMaxDynamicSharedMemorySize, PROJ_SMEM);
    cudaFuncSetAttribute(attn_mma3,
                         cudaFuncAttributeMaxDynamicSharedMemorySize, ATTN_SMEM);

    split_all_kernel<<<9216, 256>>>(x, Wq, Wk, Wv, Wu, Wo, x2, w5);

    proj_fused<<<dim3(32, 32), 256, PROJ_SMEM>>>(
        x2, w5, bq, bk, bv, bu, q2, k2, v2, up);

    attn_mma3<<<dim3(SEQ / 128, 32), 256, ATTN_SMEM>>>(q2, k2, v2, ap);

    ln_gate<<<MTOT, 256>>>(ap, up, ln_g, ln_b, g2);

    proj_out<<<dim3(8, 32), 256, PROJ_SMEM>>>(
        g2, w5 + (size_t)4096 * 2048, bo, (float*)d_out);
}